// round 13
// baseline (speedup 1.0000x reference)
#include <cuda_runtime.h>
#include <cstdint>

// Problem constants (fixed by setup_inputs)
#define BS 4
#define NN 1024
#define GD 6
#define CC 256
#define HH 8
#define DH 32
#define MC 64
#define HID 16

// ---------------- scratch (device globals; no allocation allowed) ----------
__device__ int   g_nbhd [BS * NN * MC];     // neighbor indices
__device__ float g_q[BS * NN * CC];
__device__ float g_k[BS * NN * CC];
__device__ float g_v[BS * NN * CC];
__device__ float g_ao[BS * NN * CC];        // attention output before W_out
__device__ unsigned char g_mask[BS * NN];   // normalized mask (0/1)

__device__ __forceinline__ float swishf(float x) {
    return x / (1.0f + __expf(-x));
}

// ---------------- Kernel 0: normalize mask regardless of bool/int32 layout -
__global__ void mask_norm_kernel(const unsigned char* __restrict__ raw) {
    __shared__ int flag;
    if (threadIdx.x == 0) flag = 0;
    __syncthreads();
    int local = 0;
    for (int i = threadIdx.x; i < BS * NN; i += 256)
        if ((i & 3) != 0 && raw[i]) local = 1;
    if (local) atomicOr(&flag, 1);
    __syncthreads();
    bool is_bytes = (flag != 0);
    const int* ri = (const int*)raw;
    for (int i = threadIdx.x; i < BS * NN; i += 256)
        g_mask[i] = is_bytes ? (raw[i] != 0 ? 1 : 0) : (ri[i] != 0 ? 1 : 0);
}

// ---------------- Kernel B: fused distances + top-64 + pass-through copy ---
__global__ void topk_kernel(const float* __restrict__ g, float* __restrict__ out_g) {
    __shared__ unsigned int skey[NN];
    __shared__ unsigned int hist[256];
    __shared__ unsigned int cum[256];
    __shared__ unsigned int warpsum[8];
    __shared__ unsigned int s_prefix, s_total_lt, s_rt;
    __shared__ int s_bin;
    __shared__ unsigned int c_lt, c_eq;

    int row = blockIdx.x;                    // b*N + i
    int b = row >> 10;
    int t = threadIdx.x;                     // 256 threads
    int lane = t & 31, w = t >> 5;

    {
        const float4* gb = (const float4*)(g + (size_t)row * NN * GD);
        float4 v[6];
        #pragma unroll
        for (int j = 0; j < 6; j++) v[j] = gb[t * 6 + j];
        float d0 = v[0].x*v[0].x + v[0].y*v[0].y + v[0].z*v[0].z + v[0].w*v[0].w
                 + v[1].x*v[1].x + v[1].y*v[1].y;
        float d1 = v[1].z*v[1].z + v[1].w*v[1].w + v[2].x*v[2].x + v[2].y*v[2].y
                 + v[2].z*v[2].z + v[2].w*v[2].w;
        float d2 = v[3].x*v[3].x + v[3].y*v[3].y + v[3].z*v[3].z + v[3].w*v[3].w
                 + v[4].x*v[4].x + v[4].y*v[4].y;
        float d3 = v[4].z*v[4].z + v[4].w*v[4].w + v[5].x*v[5].x + v[5].y*v[5].y
                 + v[5].z*v[5].z + v[5].w*v[5].w;
        uchar4 mk = ((const uchar4*)g_mask)[(b << 8) + t];
        if (!mk.x) d0 = 1e16f;
        if (!mk.y) d1 = 1e16f;
        if (!mk.z) d2 = 1e16f;
        if (!mk.w) d3 = 1e16f;
        skey[4*t + 0] = __float_as_uint(d0);
        skey[4*t + 1] = __float_as_uint(d1);
        skey[4*t + 2] = __float_as_uint(d2);
        skey[4*t + 3] = __float_as_uint(d3);
        if (out_g) {
            float4* ob = (float4*)(out_g + (size_t)row * NN * GD);
            #pragma unroll
            for (int j = 0; j < 6; j++) ob[t * 6 + j] = v[j];
        }
    }
    if (t == 0) { s_prefix = 0u; s_total_lt = 0u; s_rt = MC; }
    __syncthreads();

    #pragma unroll
    for (int pass = 0; pass < 4; pass++) {
        int shift = 24 - pass * 8;
        unsigned int pmask = (pass == 0) ? 0u : (0xFFFFFFFFu << (shift + 8));
        hist[t] = 0u;
        __syncthreads();
        unsigned int prefix = s_prefix;
        #pragma unroll
        for (int r = 0; r < 4; r++) {
            unsigned int key = skey[t + r * 256];
            if ((key & pmask) == prefix)
                atomicAdd(&hist[(key >> shift) & 0xFFu], 1u);
        }
        __syncthreads();
        unsigned int inc = hist[t];
        #pragma unroll
        for (int o = 1; o < 32; o <<= 1) {
            unsigned int u = __shfl_up_sync(0xFFFFFFFFu, inc, o);
            if (lane >= o) inc += u;
        }
        if (lane == 31) warpsum[w] = inc;
        __syncthreads();
        if (w == 0) {
            unsigned int ws = (lane < 8) ? warpsum[lane] : 0u;
            #pragma unroll
            for (int o = 1; o < 8; o <<= 1) {
                unsigned int u = __shfl_up_sync(0xFFFFFFFFu, ws, o);
                if (lane >= o) ws += u;
            }
            if (lane < 8) warpsum[lane] = ws;
        }
        __syncthreads();
        unsigned int incl = inc + (w > 0 ? warpsum[w - 1] : 0u);
        cum[t] = incl;
        __syncthreads();
        unsigned int rt = s_rt;
        unsigned int prev = (t == 0) ? 0u : cum[t - 1];
        if (incl >= rt && prev < rt) s_bin = t;
        __syncthreads();
        if (t == 0) {
            int bin = s_bin;
            unsigned int cb = (bin == 0) ? 0u : cum[bin - 1];
            s_total_lt += cb;
            s_rt = s_rt - cb;
            s_prefix = s_prefix | ((unsigned int)bin << shift);
        }
        __syncthreads();
    }

    unsigned int T = s_prefix;
    unsigned int total_lt = s_total_lt;
    if (t == 0) { c_lt = 0u; c_eq = 0u; }
    __syncthreads();
    int* outp = g_nbhd + row * MC;
    #pragma unroll
    for (int r = 0; r < 4; r++) {
        int e = t + r * 256;
        unsigned int key = skey[e];
        if (key < T) {
            unsigned int pos = atomicAdd(&c_lt, 1u);
            outp[pos] = e;
        } else if (key == T) {
            unsigned int pe = atomicAdd(&c_eq, 1u);
            unsigned int pos = total_lt + pe;
            if (pos < MC) outp[pos] = e;
        }
    }
}

// ---------------- GEMM 128x64 tile, 8x4 microtile, K=256 -------------------
__device__ __forceinline__ void gemm_tile_128x64(
    const float* __restrict__ A, const float* __restrict__ B,
    const float* __restrict__ bias, float* __restrict__ C,
    int mb, int col0)
{
    __shared__ float As[16][132];
    __shared__ float Bsh[16][64];
    float acc[8][4];
    #pragma unroll
    for (int i = 0; i < 8; i++)
        #pragma unroll
        for (int j = 0; j < 4; j++) acc[i][j] = 0.f;

    int t = threadIdx.x;
    int tm = t >> 4, tn = t & 15;

    for (int k0 = 0; k0 < CC; k0 += 16) {
        #pragma unroll
        for (int r = 0; r < 2; r++) {
            int idx = t + r * 256;
            int m = idx >> 2, kq = idx & 3;
            float4 a = *(const float4*)(A + (size_t)(mb + m) * CC + k0 + kq * 4);
            As[kq*4+0][m] = a.x; As[kq*4+1][m] = a.y;
            As[kq*4+2][m] = a.z; As[kq*4+3][m] = a.w;
        }
        {
            int kk = t >> 4, n4 = t & 15;
            float4 b4 = *(const float4*)(B + (size_t)(k0 + kk) * CC + col0 + n4 * 4);
            *(float4*)&Bsh[kk][n4 * 4] = b4;
        }
        __syncthreads();
        #pragma unroll
        for (int kk = 0; kk < 16; kk++) {
            float a[8], b[4];
            #pragma unroll
            for (int i = 0; i < 8; i++) a[i] = As[kk][tm * 8 + i];
            #pragma unroll
            for (int j = 0; j < 4; j++) b[j] = Bsh[kk][tn * 4 + j];
            #pragma unroll
            for (int i = 0; i < 8; i++)
                #pragma unroll
                for (int j = 0; j < 4; j++) acc[i][j] += a[i] * b[j];
        }
        __syncthreads();
    }
    #pragma unroll
    for (int i = 0; i < 8; i++)
        #pragma unroll
        for (int j = 0; j < 4; j++)
            C[(size_t)(mb + tm*8 + i) * CC + col0 + tn*4 + j] = acc[i][j] + bias[col0 + tn*4 + j];
}

__global__ void __launch_bounds__(256) qkv_gemm_kernel(
    const float* __restrict__ A,
    const float* __restrict__ Wq, const float* __restrict__ bq,
    const float* __restrict__ Wk, const float* __restrict__ bk,
    const float* __restrict__ Wv, const float* __restrict__ bv)
{
    int mb = blockIdx.x * 128;
    int yb = blockIdx.y;
    int which = yb >> 2;
    int col0 = (yb & 3) * 64;
    const float* B  = which == 0 ? Wq : (which == 1 ? Wk : Wv);
    const float* bi = which == 0 ? bq : (which == 1 ? bk : bv);
    float* C = which == 0 ? g_q : (which == 1 ? g_k : g_v);
    gemm_tile_128x64(A, B, bi, C, mb, col0);
}

__global__ void __launch_bounds__(256) out_gemm_kernel(
    const float* __restrict__ B, const float* __restrict__ bias,
    float* __restrict__ C)
{
    gemm_tile_128x64(g_ao, B, bias, C, blockIdx.x * 128, blockIdx.y * 64);
}

// ---------------- Kernel D: fused loc-MLP + feature + softmax + AV ---------
// MLP weights stored TRANSPOSED in smem so inner loops read contiguous 16B
// (LDS.128): sW1T[h][k2][gg pad 8], sW2T[h][l][k2].
__global__ void __launch_bounds__(256) score_kernel(
                            const float* __restrict__ g,
                            const float* __restrict__ lW1, const float* __restrict__ lb1,
                            const float* __restrict__ lW2, const float* __restrict__ lb2,
                            const float* __restrict__ lW3, const float* __restrict__ lb3) {
    __shared__ float sW1T[HH * HID * 8];     // 1024: [h][k2][gg(0..5), pad]
    __shared__ float sB1[HH * HID];
    __shared__ float sW2T[HH * HID * HID];   // 2048: [h][l][k2]
    __shared__ float sB2[HH * HID];
    __shared__ float sW3[HH * HID];
    __shared__ float sB3[HH];
    __shared__ float sng[MC * 7];
    __shared__ float sq[CC];
    __shared__ float sscore[HH * MC];
    __shared__ int   snidx[MC];
    __shared__ int   snm[MC];

    int i = blockIdx.x;
    int b = blockIdx.y;
    int t = threadIdx.x;
    int h = t >> 5;
    int lane = t & 31;
    int row = b * NN + i;
    const size_t bN = (size_t)(b * NN);

    // transposed cooperative weight loads
    for (int x = t; x < HH * HID * 8; x += 256) {
        int hh = x >> 7, k2 = (x >> 3) & 15, gg = x & 7;
        sW1T[x] = (gg < GD) ? lW1[hh * (GD * HID) + gg * HID + k2] : 0.f;
    }
    for (int x = t; x < HH * HID * HID; x += 256) {
        int hh = x >> 8, l = (x >> 4) & 15, k2 = x & 15;
        sW2T[x] = lW2[hh * (HID * HID) + k2 * HID + l];
    }
    for (int x = t; x < HH * HID; x += 256) sB1[x] = lb1[x];
    for (int x = t; x < HH * HID; x += 256) sB2[x] = lb2[x];
    for (int x = t; x < HH * HID; x += 256) sW3[x] = lW3[x];
    if (t < HH) sB3[t] = lb3[t];

    if (t < MC) {
        int id = g_nbhd[row * MC + t];
        snidx[t] = id;
        snm[t] = g_mask[b * NN + id] != 0 ? 1 : 0;
    }
    sq[t] = g_q[(size_t)row * CC + t];
    __syncthreads();

    for (int x = t; x < MC * GD; x += 256) {
        int m = x / GD, gk = x - m * GD;
        sng[m * 7 + gk] = g[(((size_t)row) * NN + snidx[m]) * GD + gk];
    }
    __syncthreads();

    // ---- Phase 1: location MLP (layers 2+3 fused); warp = head
    {
        float xa[8], xb[8];
        #pragma unroll
        for (int gg = 0; gg < GD; gg++) {
            xa[gg] = sng[lane * 7 + gg];
            xb[gg] = sng[(lane + 32) * 7 + gg];
        }
        xa[6] = xa[7] = 0.f; xb[6] = xb[7] = 0.f;
        float h1a[HID], h1b[HID];
        #pragma unroll
        for (int k2 = 0; k2 < HID; k2++) {
            const float4* wr = (const float4*)&sW1T[(h * HID + k2) * 8];
            float4 w0 = wr[0], w1 = wr[1];
            float aa = sB1[h * HID + k2];
            float ab = aa;
            aa += xa[0]*w0.x + xa[1]*w0.y + xa[2]*w0.z + xa[3]*w0.w
                + xa[4]*w1.x + xa[5]*w1.y + xa[6]*w1.z + xa[7]*w1.w;
            ab += xb[0]*w0.x + xb[1]*w0.y + xb[2]*w0.z + xb[3]*w0.w
                + xb[4]*w1.x + xb[5]*w1.y + xb[6]*w1.z + xb[7]*w1.w;
            h1a[k2] = swishf(aa); h1b[k2] = swishf(ab);
        }
        float oa = sB3[h], ob = oa;
        #pragma unroll
        for (int l = 0; l < HID; l++) {
            const float4* wr = (const float4*)&sW2T[(h * HID + l) * HID];
            float aa = sB2[h * HID + l], ab = aa;
            #pragma unroll
            for (int kq = 0; kq < 4; kq++) {
                float4 w = wr[kq];
                aa += h1a[kq*4+0]*w.x + h1a[kq*4+1]*w.y + h1a[kq*4+2]*w.z + h1a[kq*4+3]*w.w;
                ab += h1b[kq*4+0]*w.x + h1b[kq*4+1]*w.y + h1b[kq*4+2]*w.z + h1b[kq*4+3]*w.w;
            }
            float w3 = sW3[h * HID + l];
            oa += swishf(aa) * w3; ob += swishf(ab) * w3;
        }
        sscore[h * MC + lane]      = swishf(oa);
        sscore[h * MC + lane + 32] = swishf(ob);
    }
    __syncthreads();

    // ---- Phase 2: feature scores; warp w owns m = 8w..8w+7, coalesced
    {
        const float inv = 0.17677669529663687f;  // 1/sqrt(32)
        const float4* sq4 = (const float4*)sq;
        float4 qa = sq4[lane];
        float4 qb = sq4[lane + 32];
        int hg = lane >> 3;
        #pragma unroll
        for (int r = 0; r < 8; r++) {
            int m = h * 8 + r;
            const float4* k4 = (const float4*)(g_k + (bN + snidx[m]) * CC);
            float4 ka = k4[lane];
            float4 kb = k4[lane + 32];
            float fa = ka.x*qa.x + ka.y*qa.y + ka.z*qa.z + ka.w*qa.w;
            float fb = kb.x*qb.x + kb.y*qb.y + kb.z*qb.z + kb.w*qb.w;
            #pragma unroll
            for (int o = 4; o > 0; o >>= 1) {
                fa += __shfl_xor_sync(0xFFFFFFFFu, fa, o);
                fb += __shfl_xor_sync(0xFFFFFFFFu, fb, o);
            }
            if ((lane & 7) == 0) {
                sscore[hg * MC + m]       += fa * inv;
                sscore[(4 + hg) * MC + m] += fb * inv;
            }
        }
    }
    __syncthreads();

    // ---- Phase 3: masked softmax over m (warp = head); weights -> sscore
    {
        float s0 = snm[lane]      ? sscore[h * MC + lane]      : -1e38f;
        float s1 = snm[lane + 32] ? sscore[h * MC + lane + 32] : -1e38f;
        float mx = fmaxf(s0, s1);
        #pragma unroll
        for (int o = 16; o > 0; o >>= 1)
            mx = fmaxf(mx, __shfl_xor_sync(0xFFFFFFFFu, mx, o));
        float e0 = __expf(s0 - mx), e1 = __expf(s1 - mx);
        float sm = e0 + e1;
        #pragma unroll
        for (int o = 16; o > 0; o >>= 1)
            sm += __shfl_xor_sync(0xFFFFFFFFu, sm, o);
        float invs = 1.0f / sm;
        sscore[h * MC + lane]      = e0 * invs;
        sscore[h * MC + lane + 32] = e1 * invs;
    }
    __syncthreads();

    // ---- Phase 4: AV; thread = channel t, head = t/32 = h, coalesced V
    {
        float acc = 0.f;
        #pragma unroll 8
        for (int m = 0; m < MC; m++) {
            acc += sscore[h * MC + m] * g_v[(bN + snidx[m]) * CC + t];
        }
        g_ao[(size_t)row * CC + t] = acc;
    }
}

// ---------------- Kernel F: mask -> float tail -----------------------------
__global__ void mask_out_kernel(float* __restrict__ out_m) {
    int t = blockIdx.x * blockDim.x + threadIdx.x;
    if (t < BS * NN) out_m[t] = g_mask[t] ? 1.0f : 0.0f;
}

// ---------------- launch ---------------------------------------------------
extern "C" void kernel_launch(void* const* d_in, const int* in_sizes, int n_in,
                              void* d_out, int out_size) {
    const float*         pg   = (const float*)d_in[0];
    const float*         cf   = (const float*)d_in[1];
    const unsigned char* mask = (const unsigned char*)d_in[2];
    const float* lW1 = (const float*)d_in[3];
    const float* lb1 = (const float*)d_in[4];
    const float* lW2 = (const float*)d_in[5];
    const float* lb2 = (const float*)d_in[6];
    const float* lW3 = (const float*)d_in[7];
    const float* lb3 = (const float*)d_in[8];
    const float* Wq  = (const float*)d_in[9];
    const float* bq  = (const float*)d_in[10];
    const float* Wk  = (const float*)d_in[11];
    const float* bk  = (const float*)d_in[12];
    const float* Win = (const float*)d_in[13];
    const float* bin = (const float*)d_in[14];
    const float* Wout= (const float*)d_in[15];
    const float* bout= (const float*)d_in[16];

    const size_t GSZ = (size_t)BS * NN * NN * GD;   // 25165824
    const size_t OSZ = (size_t)BS * NN * CC;        // 1048576
    const size_t MSZ = (size_t)BS * NN;             // 4096

    float* out = (float*)d_out;
    float* out_g = nullptr;
    float* out_o = out;
    float* out_m = nullptr;
    size_t osz = (size_t)out_size;
    if (osz == GSZ + OSZ + MSZ)      { out_g = out; out_o = out + GSZ; out_m = out + GSZ + OSZ; }
    else if (osz == GSZ + OSZ)       { out_g = out; out_o = out + GSZ; }
    else if (osz == OSZ + MSZ)       { out_o = out; out_m = out + OSZ; }

    static cudaStream_t s1 = nullptr;
    static cudaEvent_t evA = nullptr, evB = nullptr;
    if (s1 == nullptr) {
        cudaStreamCreateWithFlags(&s1, cudaStreamNonBlocking);
        cudaEventCreateWithFlags(&evA, cudaEventDisableTiming);
        cudaEventCreateWithFlags(&evB, cudaEventDisableTiming);
    }

    mask_norm_kernel<<<1, 256>>>(mask);
    cudaEventRecord(evA, 0);
    cudaStreamWaitEvent(s1, evA, 0);

    // Side stream: QKV GEMM + mask tail
    qkv_gemm_kernel<<<dim3(BS * NN / 128, 12), 256, 0, s1>>>(cf, Wq, bq, Wk, bk, Win, bin);
    if (out_m) mask_out_kernel<<<(BS * NN + 255) / 256, 256, 0, s1>>>(out_m);
    cudaEventRecord(evB, s1);

    // Main stream: topk (intended to overlap with qkv)
    topk_kernel<<<BS * NN, 256>>>(pg, out_g);
    cudaStreamWaitEvent(0, evB, 0);
    score_kernel<<<dim3(NN, BS), 256>>>(pg, lW1, lb1, lW2, lb2, lW3, lb3);
    out_gemm_kernel<<<dim3(BS * NN / 128, CC / 64), 256>>>(Wout, bout, out_o);
}

// round 14
// speedup vs baseline: 1.0126x; 1.0126x over previous
#include <cuda_runtime.h>
#include <cstdint>

// Problem constants (fixed by setup_inputs)
#define BS 4
#define NN 1024
#define GD 6
#define CC 256
#define HH 8
#define DH 32
#define MC 64
#define HID 16

// ---------------- scratch (device globals; no allocation allowed) ----------
__device__ int   g_nbhd [BS * NN * MC];     // neighbor indices
__device__ float g_q[BS * NN * CC];
__device__ float g_k[BS * NN * CC];
__device__ float g_v[BS * NN * CC];
__device__ float g_ao[BS * NN * CC];        // attention output before W_out
__device__ unsigned char g_mask[BS * NN];   // normalized mask (0/1)

__device__ __forceinline__ float swishf(float x) {
    return x / (1.0f + __expf(-x));
}

// ---------------- Kernel 0: normalize mask regardless of bool/int32 layout -
__global__ void mask_norm_kernel(const unsigned char* __restrict__ raw) {
    __shared__ int flag;
    if (threadIdx.x == 0) flag = 0;
    __syncthreads();
    int local = 0;
    for (int i = threadIdx.x; i < BS * NN; i += 256)
        if ((i & 3) != 0 && raw[i]) local = 1;
    if (local) atomicOr(&flag, 1);
    __syncthreads();
    bool is_bytes = (flag != 0);
    const int* ri = (const int*)raw;
    for (int i = threadIdx.x; i < BS * NN; i += 256)
        g_mask[i] = is_bytes ? (raw[i] != 0 ? 1 : 0) : (ri[i] != 0 ? 1 : 0);
}

// ---------------- Kernel B: fused distances + top-64 + pass-through copy ---
__global__ void topk_kernel(const float* __restrict__ g, float* __restrict__ out_g) {
    __shared__ unsigned int skey[NN];
    __shared__ unsigned int hist[256];
    __shared__ unsigned int cum[256];
    __shared__ unsigned int warpsum[8];
    __shared__ unsigned int s_prefix, s_total_lt, s_rt;
    __shared__ int s_bin;
    __shared__ unsigned int c_lt, c_eq;

    int row = blockIdx.x;                    // b*N + i
    int b = row >> 10;
    int t = threadIdx.x;                     // 256 threads
    int lane = t & 31, w = t >> 5;

    {
        const float4* gb = (const float4*)(g + (size_t)row * NN * GD);
        float4 v[6];
        #pragma unroll
        for (int j = 0; j < 6; j++) v[j] = gb[t * 6 + j];
        float d0 = v[0].x*v[0].x + v[0].y*v[0].y + v[0].z*v[0].z + v[0].w*v[0].w
                 + v[1].x*v[1].x + v[1].y*v[1].y;
        float d1 = v[1].z*v[1].z + v[1].w*v[1].w + v[2].x*v[2].x + v[2].y*v[2].y
                 + v[2].z*v[2].z + v[2].w*v[2].w;
        float d2 = v[3].x*v[3].x + v[3].y*v[3].y + v[3].z*v[3].z + v[3].w*v[3].w
                 + v[4].x*v[4].x + v[4].y*v[4].y;
        float d3 = v[4].z*v[4].z + v[4].w*v[4].w + v[5].x*v[5].x + v[5].y*v[5].y
                 + v[5].z*v[5].z + v[5].w*v[5].w;
        uchar4 mk = ((const uchar4*)g_mask)[(b << 8) + t];
        if (!mk.x) d0 = 1e16f;
        if (!mk.y) d1 = 1e16f;
        if (!mk.z) d2 = 1e16f;
        if (!mk.w) d3 = 1e16f;
        skey[4*t + 0] = __float_as_uint(d0);
        skey[4*t + 1] = __float_as_uint(d1);
        skey[4*t + 2] = __float_as_uint(d2);
        skey[4*t + 3] = __float_as_uint(d3);
        if (out_g) {
            float4* ob = (float4*)(out_g + (size_t)row * NN * GD);
            #pragma unroll
            for (int j = 0; j < 6; j++) ob[t * 6 + j] = v[j];
        }
    }
    if (t == 0) { s_prefix = 0u; s_total_lt = 0u; s_rt = MC; }
    __syncthreads();

    #pragma unroll
    for (int pass = 0; pass < 4; pass++) {
        int shift = 24 - pass * 8;
        unsigned int pmask = (pass == 0) ? 0u : (0xFFFFFFFFu << (shift + 8));
        hist[t] = 0u;
        __syncthreads();
        unsigned int prefix = s_prefix;
        #pragma unroll
        for (int r = 0; r < 4; r++) {
            unsigned int key = skey[t + r * 256];
            if ((key & pmask) == prefix)
                atomicAdd(&hist[(key >> shift) & 0xFFu], 1u);
        }
        __syncthreads();
        unsigned int inc = hist[t];
        #pragma unroll
        for (int o = 1; o < 32; o <<= 1) {
            unsigned int u = __shfl_up_sync(0xFFFFFFFFu, inc, o);
            if (lane >= o) inc += u;
        }
        if (lane == 31) warpsum[w] = inc;
        __syncthreads();
        if (w == 0) {
            unsigned int ws = (lane < 8) ? warpsum[lane] : 0u;
            #pragma unroll
            for (int o = 1; o < 8; o <<= 1) {
                unsigned int u = __shfl_up_sync(0xFFFFFFFFu, ws, o);
                if (lane >= o) ws += u;
            }
            if (lane < 8) warpsum[lane] = ws;
        }
        __syncthreads();
        unsigned int incl = inc + (w > 0 ? warpsum[w - 1] : 0u);
        cum[t] = incl;
        __syncthreads();
        unsigned int rt = s_rt;
        unsigned int prev = (t == 0) ? 0u : cum[t - 1];
        if (incl >= rt && prev < rt) s_bin = t;
        __syncthreads();
        if (t == 0) {
            int bin = s_bin;
            unsigned int cb = (bin == 0) ? 0u : cum[bin - 1];
            s_total_lt += cb;
            s_rt = s_rt - cb;
            s_prefix = s_prefix | ((unsigned int)bin << shift);
        }
        __syncthreads();
    }

    unsigned int T = s_prefix;
    unsigned int total_lt = s_total_lt;
    if (t == 0) { c_lt = 0u; c_eq = 0u; }
    __syncthreads();
    int* outp = g_nbhd + row * MC;
    #pragma unroll
    for (int r = 0; r < 4; r++) {
        int e = t + r * 256;
        unsigned int key = skey[e];
        if (key < T) {
            unsigned int pos = atomicAdd(&c_lt, 1u);
            outp[pos] = e;
        } else if (key == T) {
            unsigned int pe = atomicAdd(&c_eq, 1u);
            unsigned int pos = total_lt + pe;
            if (pos < MC) outp[pos] = e;
        }
    }
}

// ---------------- GEMM 128x64 tile, 8x4 microtile, K=256 -------------------
__device__ __forceinline__ void gemm_tile_128x64(
    const float* __restrict__ A, const float* __restrict__ B,
    const float* __restrict__ bias, float* __restrict__ C,
    int mb, int col0)
{
    __shared__ float As[16][132];
    __shared__ float Bsh[16][64];
    float acc[8][4];
    #pragma unroll
    for (int i = 0; i < 8; i++)
        #pragma unroll
        for (int j = 0; j < 4; j++) acc[i][j] = 0.f;

    int t = threadIdx.x;
    int tm = t >> 4, tn = t & 15;

    for (int k0 = 0; k0 < CC; k0 += 16) {
        #pragma unroll
        for (int r = 0; r < 2; r++) {
            int idx = t + r * 256;
            int m = idx >> 2, kq = idx & 3;
            float4 a = *(const float4*)(A + (size_t)(mb + m) * CC + k0 + kq * 4);
            As[kq*4+0][m] = a.x; As[kq*4+1][m] = a.y;
            As[kq*4+2][m] = a.z; As[kq*4+3][m] = a.w;
        }
        {
            int kk = t >> 4, n4 = t & 15;
            float4 b4 = *(const float4*)(B + (size_t)(k0 + kk) * CC + col0 + n4 * 4);
            *(float4*)&Bsh[kk][n4 * 4] = b4;
        }
        __syncthreads();
        #pragma unroll
        for (int kk = 0; kk < 16; kk++) {
            float a[8], b[4];
            #pragma unroll
            for (int i = 0; i < 8; i++) a[i] = As[kk][tm * 8 + i];
            #pragma unroll
            for (int j = 0; j < 4; j++) b[j] = Bsh[kk][tn * 4 + j];
            #pragma unroll
            for (int i = 0; i < 8; i++)
                #pragma unroll
                for (int j = 0; j < 4; j++) acc[i][j] += a[i] * b[j];
        }
        __syncthreads();
    }
    #pragma unroll
    for (int i = 0; i < 8; i++)
        #pragma unroll
        for (int j = 0; j < 4; j++)
            C[(size_t)(mb + tm*8 + i) * CC + col0 + tn*4 + j] = acc[i][j] + bias[col0 + tn*4 + j];
}

__global__ void __launch_bounds__(256) qkv_gemm_kernel(
    const float* __restrict__ A,
    const float* __restrict__ Wq, const float* __restrict__ bq,
    const float* __restrict__ Wk, const float* __restrict__ bk,
    const float* __restrict__ Wv, const float* __restrict__ bv)
{
    int mb = blockIdx.x * 128;
    int yb = blockIdx.y;
    int which = yb >> 2;
    int col0 = (yb & 3) * 64;
    const float* B  = which == 0 ? Wq : (which == 1 ? Wk : Wv);
    const float* bi = which == 0 ? bq : (which == 1 ? bk : bv);
    float* C = which == 0 ? g_q : (which == 1 ? g_k : g_v);
    gemm_tile_128x64(A, B, bi, C, mb, col0);
}

__global__ void __launch_bounds__(256) out_gemm_kernel(
    const float* __restrict__ B, const float* __restrict__ bias,
    float* __restrict__ C)
{
    gemm_tile_128x64(g_ao, B, bias, C, blockIdx.x * 128, blockIdx.y * 64);
}

// ---------------- Kernel D: fused loc-MLP + feature + softmax + AV ---------
// Split by head-half: grid (NN, BS, 2), 128 threads. Block z handles heads
// hh0=4z..4z+3 and channels [128z, 128z+128) of its row.
__global__ void __launch_bounds__(128) score_kernel(
                            const float* __restrict__ g,
                            const float* __restrict__ lW1, const float* __restrict__ lb1,
                            const float* __restrict__ lW2, const float* __restrict__ lb2,
                            const float* __restrict__ lW3, const float* __restrict__ lb3) {
    __shared__ float sW1[4 * GD * HID];      // 384
    __shared__ float sB1[4 * HID];           // 64
    __shared__ float sW2[4 * HID * HID];     // 1024
    __shared__ float sB2[4 * HID];           // 64
    __shared__ float sW3[4 * HID];           // 64
    __shared__ float sB3[4];
    __shared__ float sng[MC * 7];            // 448
    __shared__ float sq[128];                // this half's q channels
    __shared__ float sscore[4 * MC];         // 256
    __shared__ int   snidx[MC];
    __shared__ int   snm[MC];

    int i = blockIdx.x;
    int b = blockIdx.y;
    int z = blockIdx.z;                      // 0 or 1
    int hh0 = z * 4;                         // first global head of this block
    int chan0 = z * 128;                     // first global channel
    int t = threadIdx.x;                     // 0..127
    int w = t >> 5;                          // local head 0..3
    int lane = t & 31;
    int row = b * NN + i;
    const size_t bN = (size_t)(b * NN);

    // cooperative weight loads for this block's 4 heads
    for (int x = t; x < 4 * GD * HID; x += 128)
        sW1[x] = lW1[hh0 * (GD * HID) + x];
    for (int x = t; x < 4 * HID * HID; x += 128)
        sW2[x] = lW2[hh0 * (HID * HID) + x];
    if (t < 4 * HID) {
        sB1[t] = lb1[hh0 * HID + t];
        sB2[t] = lb2[hh0 * HID + t];
        sW3[t] = lW3[hh0 * HID + t];
    }
    if (t < 4) sB3[t] = lb3[hh0 + t];

    if (t < MC) {
        int id = g_nbhd[row * MC + t];
        snidx[t] = id;
        snm[t] = g_mask[b * NN + id] != 0 ? 1 : 0;
    }
    sq[t] = g_q[(size_t)row * CC + chan0 + t];
    __syncthreads();

    for (int x = t; x < MC * GD; x += 128) {
        int m = x / GD, gk = x - m * GD;
        sng[m * 7 + gk] = g[(((size_t)row) * NN + snidx[m]) * GD + gk];
    }
    __syncthreads();

    // ---- Phase 1: location MLP (layers 2+3 fused); warp = local head w
    {
        float xa[GD], xb[GD];
        #pragma unroll
        for (int gg = 0; gg < GD; gg++) {
            xa[gg] = sng[lane * 7 + gg];
            xb[gg] = sng[(lane + 32) * 7 + gg];
        }
        float h1a[HID], h1b[HID];
        #pragma unroll
        for (int k2 = 0; k2 < HID; k2++) {
            float aa = sB1[w * HID + k2], ab = aa;
            #pragma unroll
            for (int gg = 0; gg < GD; gg++) {
                float wt = sW1[w * (GD * HID) + gg * HID + k2];
                aa += xa[gg] * wt; ab += xb[gg] * wt;
            }
            h1a[k2] = swishf(aa); h1b[k2] = swishf(ab);
        }
        float oa = sB3[w], ob = oa;
        #pragma unroll
        for (int l = 0; l < HID; l++) {
            float aa = sB2[w * HID + l], ab = aa;
            #pragma unroll
            for (int k2 = 0; k2 < HID; k2++) {
                float wt = sW2[w * (HID * HID) + k2 * HID + l];
                aa += h1a[k2] * wt; ab += h1b[k2] * wt;
            }
            float w3 = sW3[w * HID + l];
            oa += swishf(aa) * w3; ob += swishf(ab) * w3;
        }
        sscore[w * MC + lane]      = swishf(oa);
        sscore[w * MC + lane + 32] = swishf(ob);
    }
    __syncthreads();

    // ---- Phase 2: feature scores; warp w owns m = 16w..16w+15, coalesced
    //      lane reads this half's 128-channel slice of each K row.
    {
        const float inv = 0.17677669529663687f;  // 1/sqrt(32)
        const float4* sq4 = (const float4*)sq;   // 32 float4 = this half
        float4 qa = sq4[lane];
        int hg = lane >> 3;                      // local head of this lane
        #pragma unroll
        for (int r = 0; r < 16; r++) {
            int m = w * 16 + r;
            const float4* k4 = (const float4*)(g_k + (bN + snidx[m]) * CC + chan0);
            float4 ka = k4[lane];
            float fa = ka.x*qa.x + ka.y*qa.y + ka.z*qa.z + ka.w*qa.w;
            #pragma unroll
            for (int o = 4; o > 0; o >>= 1)
                fa += __shfl_xor_sync(0xFFFFFFFFu, fa, o);
            if ((lane & 7) == 0)
                sscore[hg * MC + m] += fa * inv;
        }
    }
    __syncthreads();

    // ---- Phase 3: masked softmax over m (warp = local head)
    {
        float s0 = snm[lane]      ? sscore[w * MC + lane]      : -1e38f;
        float s1 = snm[lane + 32] ? sscore[w * MC + lane + 32] : -1e38f;
        float mx = fmaxf(s0, s1);
        #pragma unroll
        for (int o = 16; o > 0; o >>= 1)
            mx = fmaxf(mx, __shfl_xor_sync(0xFFFFFFFFu, mx, o));
        float e0 = __expf(s0 - mx), e1 = __expf(s1 - mx);
        float sm = e0 + e1;
        #pragma unroll
        for (int o = 16; o > 0; o >>= 1)
            sm += __shfl_xor_sync(0xFFFFFFFFu, sm, o);
        float invs = 1.0f / sm;
        sscore[w * MC + lane]      = e0 * invs;
        sscore[w * MC + lane + 32] = e1 * invs;
    }
    __syncthreads();

    // ---- Phase 4: AV; thread = local channel t (head = t/32 = w)
    {
        float acc = 0.f;
        #pragma unroll 8
        for (int m = 0; m < MC; m++) {
            acc += sscore[w * MC + m] * g_v[(bN + snidx[m]) * CC + chan0 + t];
        }
        g_ao[(size_t)row * CC + chan0 + t] = acc;
    }
}

// ---------------- Kernel F: mask -> float tail -----------------------------
__global__ void mask_out_kernel(float* __restrict__ out_m) {
    int t = blockIdx.x * blockDim.x + threadIdx.x;
    if (t < BS * NN) out_m[t] = g_mask[t] ? 1.0f : 0.0f;
}

// ---------------- launch ---------------------------------------------------
extern "C" void kernel_launch(void* const* d_in, const int* in_sizes, int n_in,
                              void* d_out, int out_size) {
    const float*         pg   = (const float*)d_in[0];
    const float*         cf   = (const float*)d_in[1];
    const unsigned char* mask = (const unsigned char*)d_in[2];
    const float* lW1 = (const float*)d_in[3];
    const float* lb1 = (const float*)d_in[4];
    const float* lW2 = (const float*)d_in[5];
    const float* lb2 = (const float*)d_in[6];
    const float* lW3 = (const float*)d_in[7];
    const float* lb3 = (const float*)d_in[8];
    const float* Wq  = (const float*)d_in[9];
    const float* bq  = (const float*)d_in[10];
    const float* Wk  = (const float*)d_in[11];
    const float* bk  = (const float*)d_in[12];
    const float* Win = (const float*)d_in[13];
    const float* bin = (const float*)d_in[14];
    const float* Wout= (const float*)d_in[15];
    const float* bout= (const float*)d_in[16];

    const size_t GSZ = (size_t)BS * NN * NN * GD;   // 25165824
    const size_t OSZ = (size_t)BS * NN * CC;        // 1048576
    const size_t MSZ = (size_t)BS * NN;             // 4096

    float* out = (float*)d_out;
    float* out_g = nullptr;
    float* out_o = out;
    float* out_m = nullptr;
    size_t osz = (size_t)out_size;
    if (osz == GSZ + OSZ + MSZ)      { out_g = out; out_o = out + GSZ; out_m = out + GSZ + OSZ; }
    else if (osz == GSZ + OSZ)       { out_g = out; out_o = out + GSZ; }
    else if (osz == OSZ + MSZ)       { out_o = out; out_m = out + OSZ; }

    static cudaStream_t s1 = nullptr;
    static cudaEvent_t evA = nullptr, evB = nullptr;
    if (s1 == nullptr) {
        cudaStreamCreateWithFlags(&s1, cudaStreamNonBlocking);
        cudaEventCreateWithFlags(&evA, cudaEventDisableTiming);
        cudaEventCreateWithFlags(&evB, cudaEventDisableTiming);
    }

    mask_norm_kernel<<<1, 256>>>(mask);
    cudaEventRecord(evA, 0);
    cudaStreamWaitEvent(s1, evA, 0);

    // Side stream: QKV GEMM + mask tail
    qkv_gemm_kernel<<<dim3(BS * NN / 128, 12), 256, 0, s1>>>(cf, Wq, bq, Wk, bk, Win, bin);
    if (out_m) mask_out_kernel<<<(BS * NN + 255) / 256, 256, 0, s1>>>(out_m);
    cudaEventRecord(evB, s1);

    // Main stream: topk (intended to overlap with qkv)
    topk_kernel<<<BS * NN, 256>>>(pg, out_g);
    cudaStreamWaitEvent(0, evB, 0);
    score_kernel<<<dim3(NN, BS, 2), 128>>>(pg, lW1, lb1, lW2, lb2, lW3, lb3);
    out_gemm_kernel<<<dim3(BS * NN / 128, CC / 64), 256>>>(Wout, bout, out_o);
}

// round 15
// speedup vs baseline: 1.0523x; 1.0391x over previous
#include <cuda_runtime.h>
#include <cstdint>

// Problem constants (fixed by setup_inputs)
#define BS 4
#define NN 1024
#define GD 6
#define CC 256
#define HH 8
#define DH 32
#define MC 64
#define HID 16

// ---------------- scratch (device globals; no allocation allowed) ----------
__device__ int   g_nbhd [BS * NN * MC];     // neighbor indices
__device__ float g_q[BS * NN * CC];
__device__ float g_k[BS * NN * CC];
__device__ float g_v[BS * NN * CC];
__device__ float g_ao[BS * NN * CC];        // attention output before W_out
__device__ unsigned char g_mask[BS * NN];   // normalized mask (0/1)

__device__ __forceinline__ float swishf(float x) {
    return x / (1.0f + __expf(-x));
}

// ---------------- Kernel 0: normalize mask regardless of bool/int32 layout -
__global__ void mask_norm_kernel(const unsigned char* __restrict__ raw) {
    __shared__ int flag;
    if (threadIdx.x == 0) flag = 0;
    __syncthreads();
    int local = 0;
    for (int i = threadIdx.x; i < BS * NN; i += 256)
        if ((i & 3) != 0 && raw[i]) local = 1;
    if (local) atomicOr(&flag, 1);
    __syncthreads();
    bool is_bytes = (flag != 0);
    const int* ri = (const int*)raw;
    for (int i = threadIdx.x; i < BS * NN; i += 256)
        g_mask[i] = is_bytes ? (raw[i] != 0 ? 1 : 0) : (ri[i] != 0 ? 1 : 0);
}

// ---------------- Kernel B: fused distances + top-64 + pass-through copy ---
__global__ void topk_kernel(const float* __restrict__ g, float* __restrict__ out_g) {
    __shared__ unsigned int skey[NN];
    __shared__ unsigned int hist[256];
    __shared__ unsigned int cum[256];
    __shared__ unsigned int warpsum[8];
    __shared__ unsigned int s_prefix, s_total_lt, s_rt;
    __shared__ int s_bin;
    __shared__ unsigned int c_lt, c_eq;

    int row = blockIdx.x;                    // b*N + i
    int b = row >> 10;
    int t = threadIdx.x;                     // 256 threads
    int lane = t & 31, w = t >> 5;

    {
        const float4* gb = (const float4*)(g + (size_t)row * NN * GD);
        float4 v[6];
        #pragma unroll
        for (int j = 0; j < 6; j++) v[j] = gb[t * 6 + j];
        float d0 = v[0].x*v[0].x + v[0].y*v[0].y + v[0].z*v[0].z + v[0].w*v[0].w
                 + v[1].x*v[1].x + v[1].y*v[1].y;
        float d1 = v[1].z*v[1].z + v[1].w*v[1].w + v[2].x*v[2].x + v[2].y*v[2].y
                 + v[2].z*v[2].z + v[2].w*v[2].w;
        float d2 = v[3].x*v[3].x + v[3].y*v[3].y + v[3].z*v[3].z + v[3].w*v[3].w
                 + v[4].x*v[4].x + v[4].y*v[4].y;
        float d3 = v[4].z*v[4].z + v[4].w*v[4].w + v[5].x*v[5].x + v[5].y*v[5].y
                 + v[5].z*v[5].z + v[5].w*v[5].w;
        uchar4 mk = ((const uchar4*)g_mask)[(b << 8) + t];
        if (!mk.x) d0 = 1e16f;
        if (!mk.y) d1 = 1e16f;
        if (!mk.z) d2 = 1e16f;
        if (!mk.w) d3 = 1e16f;
        skey[4*t + 0] = __float_as_uint(d0);
        skey[4*t + 1] = __float_as_uint(d1);
        skey[4*t + 2] = __float_as_uint(d2);
        skey[4*t + 3] = __float_as_uint(d3);
        if (out_g) {
            float4* ob = (float4*)(out_g + (size_t)row * NN * GD);
            #pragma unroll
            for (int j = 0; j < 6; j++) ob[t * 6 + j] = v[j];
        }
    }
    if (t == 0) { s_prefix = 0u; s_total_lt = 0u; s_rt = MC; }
    __syncthreads();

    #pragma unroll
    for (int pass = 0; pass < 4; pass++) {
        int shift = 24 - pass * 8;
        unsigned int pmask = (pass == 0) ? 0u : (0xFFFFFFFFu << (shift + 8));
        hist[t] = 0u;
        __syncthreads();
        unsigned int prefix = s_prefix;
        #pragma unroll
        for (int r = 0; r < 4; r++) {
            unsigned int key = skey[t + r * 256];
            if ((key & pmask) == prefix)
                atomicAdd(&hist[(key >> shift) & 0xFFu], 1u);
        }
        __syncthreads();
        unsigned int inc = hist[t];
        #pragma unroll
        for (int o = 1; o < 32; o <<= 1) {
            unsigned int u = __shfl_up_sync(0xFFFFFFFFu, inc, o);
            if (lane >= o) inc += u;
        }
        if (lane == 31) warpsum[w] = inc;
        __syncthreads();
        if (w == 0) {
            unsigned int ws = (lane < 8) ? warpsum[lane] : 0u;
            #pragma unroll
            for (int o = 1; o < 8; o <<= 1) {
                unsigned int u = __shfl_up_sync(0xFFFFFFFFu, ws, o);
                if (lane >= o) ws += u;
            }
            if (lane < 8) warpsum[lane] = ws;
        }
        __syncthreads();
        unsigned int incl = inc + (w > 0 ? warpsum[w - 1] : 0u);
        cum[t] = incl;
        __syncthreads();
        unsigned int rt = s_rt;
        unsigned int prev = (t == 0) ? 0u : cum[t - 1];
        if (incl >= rt && prev < rt) s_bin = t;
        __syncthreads();
        if (t == 0) {
            int bin = s_bin;
            unsigned int cb = (bin == 0) ? 0u : cum[bin - 1];
            s_total_lt += cb;
            s_rt = s_rt - cb;
            s_prefix = s_prefix | ((unsigned int)bin << shift);
        }
        __syncthreads();
    }

    unsigned int T = s_prefix;
    unsigned int total_lt = s_total_lt;
    if (t == 0) { c_lt = 0u; c_eq = 0u; }
    __syncthreads();
    int* outp = g_nbhd + row * MC;
    #pragma unroll
    for (int r = 0; r < 4; r++) {
        int e = t + r * 256;
        unsigned int key = skey[e];
        if (key < T) {
            unsigned int pos = atomicAdd(&c_lt, 1u);
            outp[pos] = e;
        } else if (key == T) {
            unsigned int pe = atomicAdd(&c_eq, 1u);
            unsigned int pos = total_lt + pe;
            if (pos < MC) outp[pos] = e;
        }
    }
}

// ---------------- tf32 MMA helpers -----------------------------------------
__device__ __forceinline__ uint32_t f32_to_tf32(float x) {
    uint32_t r;
    asm("cvt.rna.tf32.f32 %0, %1;" : "=r"(r) : "f"(x));
    return r;
}

__device__ __forceinline__ void mma_tf32(float c[4], const uint32_t a[4], const uint32_t b[2]) {
    asm("mma.sync.aligned.m16n8k8.row.col.f32.tf32.tf32.f32 "
        "{%0,%1,%2,%3}, {%4,%5,%6,%7}, {%8,%9}, {%0,%1,%2,%3};"
        : "+f"(c[0]), "+f"(c[1]), "+f"(c[2]), "+f"(c[3])
        : "r"(a[0]), "r"(a[1]), "r"(a[2]), "r"(a[3]), "r"(b[0]), "r"(b[1]));
}

// ---------------- GEMM 128x64 tile via 3xTF32 tensor-core MMA --------------
// 8 warps: wm = w>>1 (M 32-slab of 2 m16 tiles), wn = w&1 (N 32-slab of 4 n8
// tiles). K chunked by 16 in smem (As transposed [k][m]), 2 k8 MMA steps.
__device__ __forceinline__ void gemm_tile_128x64(
    const float* __restrict__ A, const float* __restrict__ B,
    const float* __restrict__ bias, float* __restrict__ C,
    int mb, int col0)
{
    __shared__ float As[16][132];
    __shared__ float Bsh[16][68];
    int t = threadIdx.x;
    int lane = t & 31, w = t >> 5;
    int gid = lane >> 2, tid = lane & 3;
    int wm = w >> 1, wn = w & 1;

    float acc[2][4][4];
    #pragma unroll
    for (int mt = 0; mt < 2; mt++)
        #pragma unroll
        for (int nt = 0; nt < 4; nt++)
            #pragma unroll
            for (int rr = 0; rr < 4; rr++) acc[mt][nt][rr] = 0.f;

    for (int k0 = 0; k0 < CC; k0 += 16) {
        #pragma unroll
        for (int r = 0; r < 2; r++) {
            int idx = t + r * 256;
            int m = idx >> 2, kq = idx & 3;
            float4 a = *(const float4*)(A + (size_t)(mb + m) * CC + k0 + kq * 4);
            As[kq*4+0][m] = a.x; As[kq*4+1][m] = a.y;
            As[kq*4+2][m] = a.z; As[kq*4+3][m] = a.w;
        }
        {
            int kk = t >> 4, n4 = t & 15;
            float4 b4 = *(const float4*)(B + (size_t)(k0 + kk) * CC + col0 + n4 * 4);
            *(float4*)&Bsh[kk][n4 * 4] = b4;
        }
        __syncthreads();
        #pragma unroll
        for (int ks = 0; ks < 2; ks++) {
            int kb = ks * 8;
            uint32_t ahi[2][4], alo[2][4], bhi[4][2], blo[4][2];
            #pragma unroll
            for (int mt = 0; mt < 2; mt++) {
                int mbase = wm * 32 + mt * 16;
                float f0 = As[kb + tid][mbase + gid];
                float f1 = As[kb + tid][mbase + gid + 8];
                float f2 = As[kb + tid + 4][mbase + gid];
                float f3 = As[kb + tid + 4][mbase + gid + 8];
                ahi[mt][0] = f32_to_tf32(f0); alo[mt][0] = f32_to_tf32(f0 - __uint_as_float(ahi[mt][0]));
                ahi[mt][1] = f32_to_tf32(f1); alo[mt][1] = f32_to_tf32(f1 - __uint_as_float(ahi[mt][1]));
                ahi[mt][2] = f32_to_tf32(f2); alo[mt][2] = f32_to_tf32(f2 - __uint_as_float(ahi[mt][2]));
                ahi[mt][3] = f32_to_tf32(f3); alo[mt][3] = f32_to_tf32(f3 - __uint_as_float(ahi[mt][3]));
            }
            #pragma unroll
            for (int nt = 0; nt < 4; nt++) {
                int nbase = wn * 32 + nt * 8;
                float f0 = Bsh[kb + tid][nbase + gid];
                float f1 = Bsh[kb + tid + 4][nbase + gid];
                bhi[nt][0] = f32_to_tf32(f0); blo[nt][0] = f32_to_tf32(f0 - __uint_as_float(bhi[nt][0]));
                bhi[nt][1] = f32_to_tf32(f1); blo[nt][1] = f32_to_tf32(f1 - __uint_as_float(bhi[nt][1]));
            }
            #pragma unroll
            for (int mt = 0; mt < 2; mt++)
                #pragma unroll
                for (int nt = 0; nt < 4; nt++) {
                    mma_tf32(acc[mt][nt], ahi[mt], bhi[nt]);
                    mma_tf32(acc[mt][nt], alo[mt], bhi[nt]);
                    mma_tf32(acc[mt][nt], ahi[mt], blo[nt]);
                }
        }
        __syncthreads();
    }

    #pragma unroll
    for (int mt = 0; mt < 2; mt++) {
        int row = mb + wm * 32 + mt * 16 + gid;
        #pragma unroll
        for (int nt = 0; nt < 4; nt++) {
            int col = col0 + wn * 32 + nt * 8 + 2 * tid;
            float b0 = bias[col], b1 = bias[col + 1];
            C[(size_t)row * CC + col]           = acc[mt][nt][0] + b0;
            C[(size_t)row * CC + col + 1]       = acc[mt][nt][1] + b1;
            C[(size_t)(row + 8) * CC + col]     = acc[mt][nt][2] + b0;
            C[(size_t)(row + 8) * CC + col + 1] = acc[mt][nt][3] + b1;
        }
    }
}

__global__ void __launch_bounds__(256) qkv_gemm_kernel(
    const float* __restrict__ A,
    const float* __restrict__ Wq, const float* __restrict__ bq,
    const float* __restrict__ Wk, const float* __restrict__ bk,
    const float* __restrict__ Wv, const float* __restrict__ bv)
{
    int mb = blockIdx.x * 128;
    int yb = blockIdx.y;
    int which = yb >> 2;
    int col0 = (yb & 3) * 64;
    const float* B  = which == 0 ? Wq : (which == 1 ? Wk : Wv);
    const float* bi = which == 0 ? bq : (which == 1 ? bk : bv);
    float* C = which == 0 ? g_q : (which == 1 ? g_k : g_v);
    gemm_tile_128x64(A, B, bi, C, mb, col0);
}

__global__ void __launch_bounds__(256) out_gemm_kernel(
    const float* __restrict__ B, const float* __restrict__ bias,
    float* __restrict__ C)
{
    gemm_tile_128x64(g_ao, B, bias, C, blockIdx.x * 128, blockIdx.y * 64);
}

// ---------------- Kernel D: fused loc-MLP + feature + softmax + AV ---------
// Split by head-half: grid (NN, BS, 2), 128 threads. Block z handles heads
// hh0=4z..4z+3 and channels [128z, 128z+128) of its row.
__global__ void __launch_bounds__(128) score_kernel(
                            const float* __restrict__ g,
                            const float* __restrict__ lW1, const float* __restrict__ lb1,
                            const float* __restrict__ lW2, const float* __restrict__ lb2,
                            const float* __restrict__ lW3, const float* __restrict__ lb3) {
    __shared__ float sW1[4 * GD * HID];      // 384
    __shared__ float sB1[4 * HID];           // 64
    __shared__ float sW2[4 * HID * HID];     // 1024
    __shared__ float sB2[4 * HID];           // 64
    __shared__ float sW3[4 * HID];           // 64
    __shared__ float sB3[4];
    __shared__ float sng[MC * 7];            // 448
    __shared__ float sq[128];                // this half's q channels
    __shared__ float sscore[4 * MC];         // 256
    __shared__ int   snidx[MC];
    __shared__ int   snm[MC];

    int i = blockIdx.x;
    int b = blockIdx.y;
    int z = blockIdx.z;                      // 0 or 1
    int hh0 = z * 4;                         // first global head of this block
    int chan0 = z * 128;                     // first global channel
    int t = threadIdx.x;                     // 0..127
    int w = t >> 5;                          // local head 0..3
    int lane = t & 31;
    int row = b * NN + i;
    const size_t bN = (size_t)(b * NN);

    // cooperative weight loads for this block's 4 heads
    for (int x = t; x < 4 * GD * HID; x += 128)
        sW1[x] = lW1[hh0 * (GD * HID) + x];
    for (int x = t; x < 4 * HID * HID; x += 128)
        sW2[x] = lW2[hh0 * (HID * HID) + x];
    if (t < 4 * HID) {
        sB1[t] = lb1[hh0 * HID + t];
        sB2[t] = lb2[hh0 * HID + t];
        sW3[t] = lW3[hh0 * HID + t];
    }
    if (t < 4) sB3[t] = lb3[hh0 + t];

    if (t < MC) {
        int id = g_nbhd[row * MC + t];
        snidx[t] = id;
        snm[t] = g_mask[b * NN + id] != 0 ? 1 : 0;
    }
    sq[t] = g_q[(size_t)row * CC + chan0 + t];
    __syncthreads();

    for (int x = t; x < MC * GD; x += 128) {
        int m = x / GD, gk = x - m * GD;
        sng[m * 7 + gk] = g[(((size_t)row) * NN + snidx[m]) * GD + gk];
    }
    __syncthreads();

    // ---- Phase 1: location MLP (layers 2+3 fused); warp = local head w
    {
        float xa[GD], xb[GD];
        #pragma unroll
        for (int gg = 0; gg < GD; gg++) {
            xa[gg] = sng[lane * 7 + gg];
            xb[gg] = sng[(lane + 32) * 7 + gg];
        }
        float h1a[HID], h1b[HID];
        #pragma unroll
        for (int k2 = 0; k2 < HID; k2++) {
            float aa = sB1[w * HID + k2], ab = aa;
            #pragma unroll
            for (int gg = 0; gg < GD; gg++) {
                float wt = sW1[w * (GD * HID) + gg * HID + k2];
                aa += xa[gg] * wt; ab += xb[gg] * wt;
            }
            h1a[k2] = swishf(aa); h1b[k2] = swishf(ab);
        }
        float oa = sB3[w], ob = oa;
        #pragma unroll
        for (int l = 0; l < HID; l++) {
            float aa = sB2[w * HID + l], ab = aa;
            #pragma unroll
            for (int k2 = 0; k2 < HID; k2++) {
                float wt = sW2[w * (HID * HID) + k2 * HID + l];
                aa += h1a[k2] * wt; ab += h1b[k2] * wt;
            }
            float w3 = sW3[w * HID + l];
            oa += swishf(aa) * w3; ob += swishf(ab) * w3;
        }
        sscore[w * MC + lane]      = swishf(oa);
        sscore[w * MC + lane + 32] = swishf(ob);
    }
    __syncthreads();

    // ---- Phase 2: feature scores; warp w owns m = 16w..16w+15, coalesced
    {
        const float inv = 0.17677669529663687f;  // 1/sqrt(32)
        const float4* sq4 = (const float4*)sq;   // 32 float4 = this half
        float4 qa = sq4[lane];
        int hg = lane >> 3;                      // local head of this lane
        #pragma unroll
        for (int r = 0; r < 16; r++) {
            int m = w * 16 + r;
            const float4* k4 = (const float4*)(g_k + (bN + snidx[m]) * CC + chan0);
            float4 ka = k4[lane];
            float fa = ka.x*qa.x + ka.y*qa.y + ka.z*qa.z + ka.w*qa.w;
            #pragma unroll
            for (int o = 4; o > 0; o >>= 1)
                fa += __shfl_xor_sync(0xFFFFFFFFu, fa, o);
            if ((lane & 7) == 0)
                sscore[hg * MC + m] += fa * inv;
        }
    }
    __syncthreads();

    // ---- Phase 3: masked softmax over m (warp = local head)
    {
        float s0 = snm[lane]      ? sscore[w * MC + lane]      : -1e38f;
        float s1 = snm[lane + 32] ? sscore[w * MC + lane + 32] : -1e38f;
        float mx = fmaxf(s0, s1);
        #pragma unroll
        for (int o = 16; o > 0; o >>= 1)
            mx = fmaxf(mx, __shfl_xor_sync(0xFFFFFFFFu, mx, o));
        float e0 = __expf(s0 - mx), e1 = __expf(s1 - mx);
        float sm = e0 + e1;
        #pragma unroll
        for (int o = 16; o > 0; o >>= 1)
            sm += __shfl_xor_sync(0xFFFFFFFFu, sm, o);
        float invs = 1.0f / sm;
        sscore[w * MC + lane]      = e0 * invs;
        sscore[w * MC + lane + 32] = e1 * invs;
    }
    __syncthreads();

    // ---- Phase 4: AV; thread = local channel t (head = t/32 = w)
    {
        float acc = 0.f;
        #pragma unroll 8
        for (int m = 0; m < MC; m++) {
            acc += sscore[w * MC + m] * g_v[(bN + snidx[m]) * CC + chan0 + t];
        }
        g_ao[(size_t)row * CC + chan0 + t] = acc;
    }
}

// ---------------- Kernel F: mask -> float tail -----------------------------
__global__ void mask_out_kernel(float* __restrict__ out_m) {
    int t = blockIdx.x * blockDim.x + threadIdx.x;
    if (t < BS * NN) out_m[t] = g_mask[t] ? 1.0f : 0.0f;
}

// ---------------- launch ---------------------------------------------------
extern "C" void kernel_launch(void* const* d_in, const int* in_sizes, int n_in,
                              void* d_out, int out_size) {
    const float*         pg   = (const float*)d_in[0];
    const float*         cf   = (const float*)d_in[1];
    const unsigned char* mask = (const unsigned char*)d_in[2];
    const float* lW1 = (const float*)d_in[3];
    const float* lb1 = (const float*)d_in[4];
    const float* lW2 = (const float*)d_in[5];
    const float* lb2 = (const float*)d_in[6];
    const float* lW3 = (const float*)d_in[7];
    const float* lb3 = (const float*)d_in[8];
    const float* Wq  = (const float*)d_in[9];
    const float* bq  = (const float*)d_in[10];
    const float* Wk  = (const float*)d_in[11];
    const float* bk  = (const float*)d_in[12];
    const float* Win = (const float*)d_in[13];
    const float* bin = (const float*)d_in[14];
    const float* Wout= (const float*)d_in[15];
    const float* bout= (const float*)d_in[16];

    const size_t GSZ = (size_t)BS * NN * NN * GD;   // 25165824
    const size_t OSZ = (size_t)BS * NN * CC;        // 1048576
    const size_t MSZ = (size_t)BS * NN;             // 4096

    float* out = (float*)d_out;
    float* out_g = nullptr;
    float* out_o = out;
    float* out_m = nullptr;
    size_t osz = (size_t)out_size;
    if (osz == GSZ + OSZ + MSZ)      { out_g = out; out_o = out + GSZ; out_m = out + GSZ + OSZ; }
    else if (osz == GSZ + OSZ)       { out_g = out; out_o = out + GSZ; }
    else if (osz == OSZ + MSZ)       { out_o = out; out_m = out + OSZ; }

    static cudaStream_t s1 = nullptr;
    static cudaEvent_t evA = nullptr, evB = nullptr;
    if (s1 == nullptr) {
        cudaStreamCreateWithFlags(&s1, cudaStreamNonBlocking);
        cudaEventCreateWithFlags(&evA, cudaEventDisableTiming);
        cudaEventCreateWithFlags(&evB, cudaEventDisableTiming);
    }

    mask_norm_kernel<<<1, 256>>>(mask);
    cudaEventRecord(evA, 0);
    cudaStreamWaitEvent(s1, evA, 0);

    // Side stream: QKV GEMM + mask tail
    qkv_gemm_kernel<<<dim3(BS * NN / 128, 12), 256, 0, s1>>>(cf, Wq, bq, Wk, bk, Win, bin);
    if (out_m) mask_out_kernel<<<(BS * NN + 255) / 256, 256, 0, s1>>>(out_m);
    cudaEventRecord(evB, s1);

    // Main stream: topk (intended to overlap with qkv)
    topk_kernel<<<BS * NN, 256>>>(pg, out_g);
    cudaStreamWaitEvent(0, evB, 0);
    score_kernel<<<dim3(NN, BS, 2), 128>>>(pg, lW1, lb1, lW2, lb2, lW3, lb3);
    out_gemm_kernel<<<dim3(BS * NN / 128, CC / 64), 256>>>(Wout, bout, out_o);
}